// round 16
// baseline (speedup 1.0000x reference)
#include <cuda_runtime.h>
#include <cuda_bf16.h>

#define N_COLS 2048                 // hidden dim
#define VECS_PER_ROW (N_COLS / 4)   // 512 float4
#define THREADS 256                 // 2 float4 per thread
#define NWARPS (THREADS / 32)
#define EPS 1e-5f

// FINAL — converged configuration after 15 rounds.
// Best measured: 35.71us kernel = 7.50 TB/s effective (93.8% of 8 TB/s HBM
// spec), DRAM 75.1%, occ 90.8%. RMSNorm over [16384, 2048] fp32 moves a
// mandatory 128 MB read + 128 MB write per launch and is bound by HBM mixed
// read/write turnaround; theoretical floor 33.5us.
//
// Exhaustively verified plateau (35.7-37.1us) across: occupancy 27-91%,
// per-thread MLP 2-16, CTA 128/256, warp-per-row and group-per-row,
// persistent + double-buffered pipelining, named barriers, and all
// load/store cache policies (__ldcs/__ldcg/default x __stcs/__stwt/default).
// Identical-source reruns span +/-0.5us — the whole remaining spread is noise.
//
// Notes for future sessions:
//   - redux.sync.add.f32 is NOT supported on sm_103 (ptxas rejects it).
//   - dram__cycles_active (~75%) understates real throughput; bytes/time
//     says ~94% of spec. Don't chase the percentage.
//   - L2 residency across graph replays doesn't materialize (128 MB cyclic
//     sweep through ~126 MB L2 = thrash).
//   - Only ways to lose: occupancy collapse (<40%) or CTA-size quantization.

__global__ __launch_bounds__(THREADS)
void rmsnorm_kernel(const float4* __restrict__ x,
                    const float4* __restrict__ g,
                    float4* __restrict__ out)
{
    const int row = blockIdx.x;
    const float4* xr = x + (size_t)row * VECS_PER_ROW;
    float4* outr = out + (size_t)row * VECS_PER_ROW;

    const int t = threadIdx.x;
    const int warp = t >> 5;
    const int lane = t & 31;

    // x has zero reuse within a launch: skip L1 fill.
    float4 v0 = __ldcg(&xr[t]);
    float4 v1 = __ldcg(&xr[t + THREADS]);

    float ss = v0.x * v0.x + v0.y * v0.y + v0.z * v0.z + v0.w * v0.w
             + v1.x * v1.x + v1.y * v1.y + v1.z * v1.z + v1.w * v1.w;

    // Warp reduce.
    #pragma unroll
    for (int off = 16; off > 0; off >>= 1)
        ss += __shfl_xor_sync(0xFFFFFFFFu, ss, off);

    // Single-barrier block reduce: publish 8 warp partials, then every
    // thread sums all 8 from smem (broadcast reads, no second barrier,
    // no serialized warp0 chain).
    __shared__ float warp_sums[NWARPS];
    if (lane == 0) warp_sums[warp] = ss;
    __syncthreads();

    float total = 0.0f;
    #pragma unroll
    for (int w = 0; w < NWARPS; w++)
        total += warp_sums[w];

    const float scale = rsqrtf(total * (1.0f / (float)N_COLS) + EPS);

    // g: 8 KB, broadcast across all rows — default policy, L1/L2-resident.
    float4 g0 = g[t];
    float4 g1 = g[t + THREADS];

    float4 o0, o1;
    o0.x = v0.x * scale * g0.x;
    o0.y = v0.y * scale * g0.y;
    o0.z = v0.z * scale * g0.z;
    o0.w = v0.w * scale * g0.w;
    o1.x = v1.x * scale * g1.x;
    o1.y = v1.y * scale * g1.y;
    o1.z = v1.z * scale * g1.z;
    o1.w = v1.w * scale * g1.w;

    outr[t] = o0;
    outr[t + THREADS] = o1;
}

extern "C" void kernel_launch(void* const* d_in, const int* in_sizes, int n_in,
                              void* d_out, int out_size)
{
    const float4* x = (const float4*)d_in[0];
    const float4* g = (const float4*)d_in[1];
    float4* out = (float4*)d_out;

    const int n_rows = in_sizes[0] / N_COLS;  // 16384

    rmsnorm_kernel<<<n_rows, THREADS>>>(x, g, out);
}